// round 1
// baseline (speedup 1.0000x reference)
#include <cuda_runtime.h>
#include <math.h>

// ---------------------------------------------------------------------------
// RockTS encoder: BS=64, NP=64 (L), NV=7, PL=16, DM=768, NH=12, DK=64, DF=3072, NL=3
// M = BS*NV*NP = 28672 rows of d_model=768
// Outputs (concatenated in d_out): z[64,7,768,64] | h_t[64,7,768,64] | attn[448,12,64,64]
// ---------------------------------------------------------------------------

#define MROWS 28672
#define DM    768
#define DF    3072
#define LSEQ  64
#define BH    448      // BS*NV
#define NHEAD 12
#define OUTSZ 22020096 // MROWS*DM

// Scratch (no cudaMalloc allowed)
__device__ float g_u[MROWS * DM];
__device__ float g_q[MROWS * DM];
__device__ float g_k[MROWS * DM];
__device__ float g_v[MROWS * DM];
__device__ float g_t[MROWS * DM];
__device__ float g_scores[BH * NHEAD * LSEQ * LSEQ];
__device__ float g_ff[MROWS * DF];
__device__ float g_stats[2 * DM];

// ---------------------------------------------------------------------------
// Generic SGEMM: C[M,N] = A[M,K] @ B[K,N] + bias, optional exact-GELU epilogue
// BM=BN=128, BK=16, 256 threads, 8x8 per thread. M,N,K all multiples of tile.
// ---------------------------------------------------------------------------
template<int GELU_EPI>
__global__ __launch_bounds__(256, 2) void gemm_kernel(
    const float* __restrict__ A, const float* __restrict__ B,
    const float* __restrict__ bias, float* __restrict__ C,
    int Mdim, int Ndim, int Kdim)
{
    __shared__ float As[16][128];
    __shared__ float Bs[16][132];

    const int tid = threadIdx.x;
    const int tx = tid & 15, ty = tid >> 4;
    const int m0 = blockIdx.y * 128, n0 = blockIdx.x * 128;

    float acc[8][8];
#pragma unroll
    for (int i = 0; i < 8; i++)
#pragma unroll
        for (int j = 0; j < 8; j++) acc[i][j] = 0.f;

    for (int k0 = 0; k0 < Kdim; k0 += 16) {
        // A tile 128x16 (512 float4)
#pragma unroll
        for (int s = 0; s < 2; s++) {
            int f4 = tid + 256 * s;
            int row = f4 >> 2, kq = (f4 & 3) * 4;
            float4 av = *(const float4*)&A[(size_t)(m0 + row) * Kdim + k0 + kq];
            As[kq + 0][row] = av.x; As[kq + 1][row] = av.y;
            As[kq + 2][row] = av.z; As[kq + 3][row] = av.w;
        }
        // B tile 16x128 (512 float4)
#pragma unroll
        for (int s = 0; s < 2; s++) {
            int f4 = tid + 256 * s;
            int row = f4 >> 5, nq = (f4 & 31) * 4;
            *(float4*)&Bs[row][nq] = *(const float4*)&B[(size_t)(k0 + row) * Ndim + n0 + nq];
        }
        __syncthreads();
#pragma unroll
        for (int k = 0; k < 16; k++) {
            float a[8], b[8];
            *(float4*)&a[0] = *(const float4*)&As[k][ty * 8];
            *(float4*)&a[4] = *(const float4*)&As[k][ty * 8 + 4];
            *(float4*)&b[0] = *(const float4*)&Bs[k][tx * 8];
            *(float4*)&b[4] = *(const float4*)&Bs[k][tx * 8 + 4];
#pragma unroll
            for (int i = 0; i < 8; i++)
#pragma unroll
                for (int j = 0; j < 8; j++) acc[i][j] += a[i] * b[j];
        }
        __syncthreads();
    }

#pragma unroll
    for (int i = 0; i < 8; i++) {
        int row = m0 + ty * 8 + i;
#pragma unroll
        for (int j = 0; j < 8; j++) {
            int col = n0 + tx * 8 + j;
            float val = acc[i][j] + bias[col];
            if (GELU_EPI)
                val = 0.5f * val * (1.0f + erff(val * 0.70710678118654752f));
            C[(size_t)row * Ndim + col] = val;
        }
    }
}

// ---------------------------------------------------------------------------
// Fused attention per (batch, head): scores (+prev), softmax, PV.
// One block per (bv, h). Dynamic smem: Qs 64*64 | Ks 64*65 | Ss 64*64 = 49408 B
// ---------------------------------------------------------------------------
__global__ __launch_bounds__(256) void attn_kernel(
    const float* __restrict__ Q, const float* __restrict__ K,
    const float* __restrict__ V, float* __restrict__ scores,
    float* __restrict__ O, float* __restrict__ attn_out, int has_prev)
{
    extern __shared__ float sm[];
    float* Qs = sm;            // 64*64
    float* Ks = sm + 4096;     // 64*65 (padded)
    float* Ss = sm + 8256;     // 64*64

    const int bh = blockIdx.x;
    const int bv = bh / NHEAD, h = bh % NHEAD;
    const int row0 = bv * LSEQ, c0 = h * 64;
    const int t = threadIdx.x;
    const size_t sb = (size_t)bh * 4096;

#pragma unroll
    for (int s = 0; s < 16; s++) {
        int e = t + 256 * s;
        int i = e >> 6, kk = e & 63;
        Qs[i * 64 + kk] = Q[(size_t)(row0 + i) * DM + c0 + kk];
        Ks[i * 65 + kk] = K[(size_t)(row0 + i) * DM + c0 + kk];
    }
    __syncthreads();

#pragma unroll 2
    for (int s = 0; s < 16; s++) {
        int e = t + 256 * s;
        int i = e >> 6, j = e & 63;
        float sum = 0.f;
#pragma unroll
        for (int kk = 0; kk < 64; kk++) sum += Qs[i * 64 + kk] * Ks[j * 65 + kk];
        float val = sum * 0.125f;
        if (has_prev) val += scores[sb + e];
        scores[sb + e] = val;
        Ss[e] = val;
    }
    __syncthreads();

    // softmax: 8 warps x 8 rows each, 2 cols per lane
    const int w = t >> 5, lane = t & 31;
#pragma unroll
    for (int p = 0; p < 8; p++) {
        int r = w * 8 + p;
        float v0 = Ss[r * 64 + lane], v1 = Ss[r * 64 + lane + 32];
        float mx = fmaxf(v0, v1);
#pragma unroll
        for (int off = 16; off > 0; off >>= 1)
            mx = fmaxf(mx, __shfl_xor_sync(0xffffffffu, mx, off));
        float e0 = __expf(v0 - mx), e1 = __expf(v1 - mx);
        float sumv = e0 + e1;
#pragma unroll
        for (int off = 16; off > 0; off >>= 1)
            sumv += __shfl_xor_sync(0xffffffffu, sumv, off);
        float inv = 1.0f / sumv;
        e0 *= inv; e1 *= inv;
        Ss[r * 64 + lane] = e0;
        Ss[r * 64 + lane + 32] = e1;
        if (attn_out) {
            attn_out[sb + r * 64 + lane] = e0;
            attn_out[sb + r * 64 + lane + 32] = e1;
        }
    }
    __syncthreads();

    // V into Ks (padded)
#pragma unroll
    for (int s = 0; s < 16; s++) {
        int e = t + 256 * s;
        int i = e >> 6, kk = e & 63;
        Ks[i * 65 + kk] = V[(size_t)(row0 + i) * DM + c0 + kk];
    }
    __syncthreads();

#pragma unroll 2
    for (int s = 0; s < 16; s++) {
        int e = t + 256 * s;
        int i = e >> 6, dk = e & 63;
        float sum = 0.f;
#pragma unroll
        for (int j = 0; j < 64; j++) sum += Ss[i * 64 + j] * Ks[j * 65 + dk];
        O[(size_t)(row0 + i) * DM + c0 + dk] = sum;
    }
}

// ---------------------------------------------------------------------------
// BatchNorm (training stats over all M rows per channel)
// ---------------------------------------------------------------------------
__global__ void zero_stats_kernel(float* stats)
{
    int idx = blockIdx.x * 256 + threadIdx.x;
    if (idx < 2 * DM) stats[idx] = 0.f;
}

// s = u + t2 (residual), write back to u, accumulate per-channel sum/sumsq
__global__ __launch_bounds__(256) void bn_add_stats_kernel(
    float* __restrict__ u, const float* __restrict__ t2, float* __restrict__ stats)
{
    const int c0 = threadIdx.x;
    float s0 = 0, s1 = 0, s2 = 0, q0 = 0, q1 = 0, q2 = 0;
    const int rbase = blockIdx.x * 128;
    for (int r = 0; r < 128; r++) {
        size_t base = (size_t)(rbase + r) * DM;
        float a0 = u[base + c0] + t2[base + c0];
        float a1 = u[base + c0 + 256] + t2[base + c0 + 256];
        float a2 = u[base + c0 + 512] + t2[base + c0 + 512];
        u[base + c0] = a0; u[base + c0 + 256] = a1; u[base + c0 + 512] = a2;
        s0 += a0; s1 += a1; s2 += a2;
        q0 += a0 * a0; q1 += a1 * a1; q2 += a2 * a2;
    }
    atomicAdd(&stats[c0], s0);
    atomicAdd(&stats[c0 + 256], s1);
    atomicAdd(&stats[c0 + 512], s2);
    atomicAdd(&stats[DM + c0], q0);
    atomicAdd(&stats[DM + c0 + 256], q1);
    atomicAdd(&stats[DM + c0 + 512], q2);
}

__global__ __launch_bounds__(256) void bn_norm_kernel(
    float* __restrict__ u, const float* __restrict__ stats,
    const float* __restrict__ g, const float* __restrict__ be)
{
    int idx = blockIdx.x * 256 + threadIdx.x;
    int c = idx % DM;
    const float invM = 1.0f / (float)MROWS;
    float mean = stats[c] * invM;
    float var = stats[DM + c] * invM - mean * mean;
    float iv = rsqrtf(var + 1e-5f);
    u[idx] = (u[idx] - mean) * iv * g[c] + be[c];
}

// ---------------------------------------------------------------------------
// Patch-embed remap: u[(b*7+v)*64+n, d] = h[(b*64+n)*7+v, d] + Wpos[n, d]
// ---------------------------------------------------------------------------
__global__ __launch_bounds__(256) void remap_embed_kernel(
    const float* __restrict__ h, const float* __restrict__ Wpos, float* __restrict__ u)
{
    int idx = blockIdx.x * 256 + threadIdx.x;
    int ru = idx / DM, d = idx % DM;
    int bv = ru >> 6, n = ru & 63;
    int b = bv / 7, v = bv % 7;
    int rh = (b * 64 + n) * 7 + v;
    u[idx] = h[(size_t)rh * DM + d] + Wpos[n * DM + d];
}

// out_h[(bv*768+d)*64+n] = h[((b*64+n)*7+v)*768+d]
__global__ void transpose_h_kernel(const float* __restrict__ h, float* __restrict__ out)
{
    __shared__ float tile[32][33];
    int bv = blockIdx.z, b = bv / 7, v = bv % 7;
    int d0 = blockIdx.x * 32, n0 = blockIdx.y * 32;
#pragma unroll
    for (int i = 0; i < 32; i += 8) {
        int n = n0 + threadIdx.y + i;
        int d = d0 + threadIdx.x;
        tile[threadIdx.y + i][threadIdx.x] = h[((size_t)(b * 64 + n) * 7 + v) * DM + d];
    }
    __syncthreads();
#pragma unroll
    for (int i = 0; i < 32; i += 8) {
        int d = d0 + threadIdx.y + i;
        int n = n0 + threadIdx.x;
        out[((size_t)bv * DM + d) * LSEQ + n] = tile[threadIdx.x][threadIdx.y + i];
    }
}

// out_z[(bv*768+d)*64+n] = u[(bv*64+n)*768+d]
__global__ void transpose_z_kernel(const float* __restrict__ u, float* __restrict__ out)
{
    __shared__ float tile[32][33];
    int bv = blockIdx.z;
    int d0 = blockIdx.x * 32, n0 = blockIdx.y * 32;
#pragma unroll
    for (int i = 0; i < 32; i += 8) {
        int n = n0 + threadIdx.y + i;
        int d = d0 + threadIdx.x;
        tile[threadIdx.y + i][threadIdx.x] = u[(size_t)(bv * 64 + n) * DM + d];
    }
    __syncthreads();
#pragma unroll
    for (int i = 0; i < 32; i += 8) {
        int d = d0 + threadIdx.y + i;
        int n = n0 + threadIdx.x;
        out[((size_t)bv * DM + d) * LSEQ + n] = tile[threadIdx.x][threadIdx.y + i];
    }
}

// ---------------------------------------------------------------------------

extern "C" void kernel_launch(void* const* d_in, const int* in_sizes, int n_in,
                              void* d_out, int out_size)
{
    const float* x    = (const float*)d_in[0];
    const float* Wp   = (const float*)d_in[1];
    const float* bp   = (const float*)d_in[2];
    const float* Wpos = (const float*)d_in[3];
    const float* Wq   = (const float*)d_in[4];
    const float* bq   = (const float*)d_in[5];
    const float* Wk   = (const float*)d_in[6];
    const float* bk   = (const float*)d_in[7];
    const float* Wv   = (const float*)d_in[8];
    const float* bv_  = (const float*)d_in[9];
    const float* Wo   = (const float*)d_in[10];
    const float* bo   = (const float*)d_in[11];
    const float* g1   = (const float*)d_in[12];
    const float* be1  = (const float*)d_in[13];
    const float* W1   = (const float*)d_in[14];
    const float* b1   = (const float*)d_in[15];
    const float* W2   = (const float*)d_in[16];
    const float* b2   = (const float*)d_in[17];
    const float* g2   = (const float*)d_in[18];
    const float* be2  = (const float*)d_in[19];

    float* out      = (float*)d_out;
    float* out_z    = out;
    float* out_h    = out + OUTSZ;
    float* out_attn = out + 2 * (size_t)OUTSZ;

    float *u, *q, *k, *v, *t, *sc, *ff, *st;
    cudaGetSymbolAddress((void**)&u,  g_u);
    cudaGetSymbolAddress((void**)&q,  g_q);
    cudaGetSymbolAddress((void**)&k,  g_k);
    cudaGetSymbolAddress((void**)&v,  g_v);
    cudaGetSymbolAddress((void**)&t,  g_t);
    cudaGetSymbolAddress((void**)&sc, g_scores);
    cudaGetSymbolAddress((void**)&ff, g_ff);
    cudaGetSymbolAddress((void**)&st, g_stats);

    cudaFuncSetAttribute(attn_kernel, cudaFuncAttributeMaxDynamicSharedMemorySize, 49408);

    const dim3 gD(DM / 128, MROWS / 128);    // N=768 GEMMs
    const dim3 gF(DF / 128, MROWS / 128);    // N=3072 GEMM
    const dim3 blk(256);
    const int elemBlocks = (MROWS * DM) / 256; // 86016
    const dim3 tgrid(24, 2, BH);
    const dim3 tblk(32, 8);

    // patch embedding: h = x @ Wp + bp  (x viewed as [28672,16])
    gemm_kernel<0><<<gD, blk>>>(x, Wp, bp, t, MROWS, DM, 16);
    remap_embed_kernel<<<elemBlocks, blk>>>(t, Wpos, u);
    transpose_h_kernel<<<tgrid, tblk>>>(t, out_h);

    for (int l = 0; l < 3; l++) {
        const float* wq = Wq + (size_t)l * DM * DM;
        const float* wk = Wk + (size_t)l * DM * DM;
        const float* wv = Wv + (size_t)l * DM * DM;
        const float* wo = Wo + (size_t)l * DM * DM;
        const float* w1 = W1 + (size_t)l * DM * DF;
        const float* w2 = W2 + (size_t)l * DF * DM;

        gemm_kernel<0><<<gD, blk>>>(u, wq, bq + l * DM, q, MROWS, DM, DM);
        gemm_kernel<0><<<gD, blk>>>(u, wk, bk + l * DM, k, MROWS, DM, DM);
        gemm_kernel<0><<<gD, blk>>>(u, wv, bv_ + l * DM, v, MROWS, DM, DM);

        attn_kernel<<<BH * NHEAD, 256, 49408>>>(
            q, k, v, sc, q /* O overwrites Q in-place, disjoint slices */,
            (l == 2) ? out_attn : nullptr, (l > 0) ? 1 : 0);

        gemm_kernel<0><<<gD, blk>>>(q, wo, bo + l * DM, t, MROWS, DM, DM);

        zero_stats_kernel<<<6, 256>>>(st);
        bn_add_stats_kernel<<<MROWS / 128, 256>>>(u, t, st);
        bn_norm_kernel<<<elemBlocks, blk>>>(u, st, g1 + l * DM, be1 + l * DM);

        gemm_kernel<1><<<gF, blk>>>(u, w1, b1 + l * DF, ff, MROWS, DF, DM);
        gemm_kernel<0><<<gD, blk>>>(ff, w2, b2 + l * DM, t, MROWS, DM, DF);

        zero_stats_kernel<<<6, 256>>>(st);
        bn_add_stats_kernel<<<MROWS / 128, 256>>>(u, t, st);
        bn_norm_kernel<<<elemBlocks, blk>>>(u, st, g2 + l * DM, be2 + l * DM);
    }

    transpose_z_kernel<<<tgrid, tblk>>>(u, out_z);
}

// round 3
// speedup vs baseline: 1.6469x; 1.6469x over previous
#include <cuda_runtime.h>
#include <math.h>
#include <stdint.h>

// ---------------------------------------------------------------------------
// RockTS encoder: BS=64, NP=64, NV=7, PL=16, DM=768, NH=12, DK=64, DF=3072, NL=3
// M = 28672 rows. Outputs: z | h_t | attn concatenated in d_out.
// R3: big GEMMs on mma.sync.m16n8k8.tf32 (legal on compute_103 PTX target).
// ---------------------------------------------------------------------------

#define MROWS 28672
#define DM    768
#define DF    3072
#define LSEQ  64
#define BH    448
#define NHEAD 12
#define OUTSZ 22020096

__device__ float g_u[MROWS * DM];
__device__ float g_q[MROWS * DM];
__device__ float g_k[MROWS * DM];
__device__ float g_v[MROWS * DM];
__device__ float g_t[MROWS * DM];
__device__ float g_scores[BH * NHEAD * LSEQ * LSEQ];
__device__ float g_ff[MROWS * DF];
__device__ float g_stats[2 * DM];
__device__ float g_wqt[3 * DM * DM];
__device__ float g_wkt[3 * DM * DM];
__device__ float g_wvt[3 * DM * DM];
__device__ float g_wot[3 * DM * DM];
__device__ float g_w1t[3 * DM * DF];
__device__ float g_w2t[3 * DF * DM];

// ---------------------------------------------------------------------------
// TF32 MMA GEMM: C[M,N] = A[M,K] @ Bt[N,K]^T + bias (optional exact GELU)
// BM=BN=128, BK=32. 256 thr, warp grid 2(m)x4(n), warp tile 64x32.
// Smem rows padded to 36 floats -> conflict-free fragment loads.
// ---------------------------------------------------------------------------
#define SROW 36
#define STAGE_F (128 * SROW)          // floats per (A or B) stage
#define MMA_SMEM (4 * STAGE_F * 4)    // bytes: A0,B0,A1,B1

__device__ __forceinline__ uint32_t f2tf32(float x) {
    uint32_t r;
    asm("cvt.rna.tf32.f32 %0, %1;" : "=r"(r) : "f"(x));
    return r;
}

template<int GELU_EPI>
__global__ __launch_bounds__(256, 1) void mma_gemm(
    const float* __restrict__ A, const float* __restrict__ Bt,
    const float* __restrict__ bias, float* __restrict__ C, int N, int K)
{
    extern __shared__ float smf[];
    float* Asm[2] = { smf,             smf + 2 * STAGE_F };
    float* Bsm[2] = { smf + STAGE_F,   smf + 3 * STAGE_F };

    const int tid  = threadIdx.x;
    const int wid  = tid >> 5, lane = tid & 31;
    const int g    = lane >> 2, tig = lane & 3;
    const int wm   = (wid & 1) * 64;     // warp m offset
    const int wn   = (wid >> 1) * 32;    // warp n offset
    const int m0   = blockIdx.y * 128, n0 = blockIdx.x * 128;

    float acc[16][4];
#pragma unroll
    for (int i = 0; i < 16; i++)
#pragma unroll
        for (int j = 0; j < 4; j++) acc[i][j] = 0.f;

    const int NK = K >> 5;

    // preload tile 0
    float4 pa[4], pb[4];
    {
        const float* Ab = A + (size_t)m0 * K;
        const float* Bb = Bt + (size_t)n0 * K;
#pragma unroll
        for (int r = 0; r < 4; r++) {
            int f = tid + 256 * r;
            int row = f >> 3, c4 = (f & 7) * 4;
            pa[r] = *(const float4*)(Ab + (size_t)row * K + c4);
            pb[r] = *(const float4*)(Bb + (size_t)row * K + c4);
        }
#pragma unroll
        for (int r = 0; r < 4; r++) {
            int f = tid + 256 * r;
            int row = f >> 3, c4 = (f & 7) * 4;
            uint32_t* da = (uint32_t*)&Asm[0][row * SROW + c4];
            uint32_t* db = (uint32_t*)&Bsm[0][row * SROW + c4];
            da[0] = f2tf32(pa[r].x); da[1] = f2tf32(pa[r].y);
            da[2] = f2tf32(pa[r].z); da[3] = f2tf32(pa[r].w);
            db[0] = f2tf32(pb[r].x); db[1] = f2tf32(pb[r].y);
            db[2] = f2tf32(pb[r].z); db[3] = f2tf32(pb[r].w);
        }
    }
    __syncthreads();

    for (int it = 0; it < NK; it++) {
        const int s = it & 1;
        // prefetch next tile (global)
        if (it + 1 < NK) {
            const float* Ab = A + (size_t)m0 * K + (it + 1) * 32;
            const float* Bb = Bt + (size_t)n0 * K + (it + 1) * 32;
#pragma unroll
            for (int r = 0; r < 4; r++) {
                int f = tid + 256 * r;
                int row = f >> 3, c4 = (f & 7) * 4;
                pa[r] = *(const float4*)(Ab + (size_t)row * K + c4);
                pb[r] = *(const float4*)(Bb + (size_t)row * K + c4);
            }
        }
        // compute current tile
        const float* As = Asm[s];
        const float* Bs = Bsm[s];
#pragma unroll
        for (int ks = 0; ks < 4; ks++) {
            const int kc = ks * 8 + tig;
            uint32_t a[4][4], b[4][2];
#pragma unroll
            for (int mt = 0; mt < 4; mt++) {
                int r0 = wm + mt * 16 + g;
                a[mt][0] = __float_as_uint(As[r0 * SROW + kc]);
                a[mt][1] = __float_as_uint(As[(r0 + 8) * SROW + kc]);
                a[mt][2] = __float_as_uint(As[r0 * SROW + kc + 4]);
                a[mt][3] = __float_as_uint(As[(r0 + 8) * SROW + kc + 4]);
            }
#pragma unroll
            for (int nt = 0; nt < 4; nt++) {
                int rn = wn + nt * 8 + g;
                b[nt][0] = __float_as_uint(Bs[rn * SROW + kc]);
                b[nt][1] = __float_as_uint(Bs[rn * SROW + kc + 4]);
            }
#pragma unroll
            for (int mt = 0; mt < 4; mt++)
#pragma unroll
                for (int nt = 0; nt < 4; nt++) {
                    float* c = acc[mt * 4 + nt];
                    asm volatile(
                        "mma.sync.aligned.m16n8k8.row.col.f32.tf32.tf32.f32 "
                        "{%0,%1,%2,%3}, {%4,%5,%6,%7}, {%8,%9}, {%0,%1,%2,%3};"
                        : "+f"(c[0]), "+f"(c[1]), "+f"(c[2]), "+f"(c[3])
                        : "r"(a[mt][0]), "r"(a[mt][1]), "r"(a[mt][2]), "r"(a[mt][3]),
                          "r"(b[nt][0]), "r"(b[nt][1]));
                }
        }
        // store next tile to the other stage
        if (it + 1 < NK) {
            float* An = Asm[s ^ 1];
            float* Bn = Bsm[s ^ 1];
#pragma unroll
            for (int r = 0; r < 4; r++) {
                int f = tid + 256 * r;
                int row = f >> 3, c4 = (f & 7) * 4;
                uint32_t* da = (uint32_t*)&An[row * SROW + c4];
                uint32_t* db = (uint32_t*)&Bn[row * SROW + c4];
                da[0] = f2tf32(pa[r].x); da[1] = f2tf32(pa[r].y);
                da[2] = f2tf32(pa[r].z); da[3] = f2tf32(pa[r].w);
                db[0] = f2tf32(pb[r].x); db[1] = f2tf32(pb[r].y);
                db[2] = f2tf32(pb[r].z); db[3] = f2tf32(pb[r].w);
            }
        }
        __syncthreads();
    }

    // epilogue: bias (+GELU), st.v2
#pragma unroll
    for (int mt = 0; mt < 4; mt++) {
#pragma unroll
        for (int nt = 0; nt < 4; nt++) {
            const float* c = acc[mt * 4 + nt];
            int col = n0 + wn + nt * 8 + 2 * tig;
            float b0 = bias[col], b1 = bias[col + 1];
            int r0 = m0 + wm + mt * 16 + g;
            float2 v0, v1;
            v0.x = c[0] + b0; v0.y = c[1] + b1;
            v1.x = c[2] + b0; v1.y = c[3] + b1;
            if (GELU_EPI) {
                v0.x = 0.5f * v0.x * (1.0f + erff(v0.x * 0.70710678118654752f));
                v0.y = 0.5f * v0.y * (1.0f + erff(v0.y * 0.70710678118654752f));
                v1.x = 0.5f * v1.x * (1.0f + erff(v1.x * 0.70710678118654752f));
                v1.y = 0.5f * v1.y * (1.0f + erff(v1.y * 0.70710678118654752f));
            }
            *(float2*)&C[(size_t)r0 * N + col] = v0;
            *(float2*)&C[(size_t)(r0 + 8) * N + col] = v1;
        }
    }
}

// ---------------------------------------------------------------------------
// fp32 SGEMM (patch embed, K=16)
// ---------------------------------------------------------------------------
__global__ __launch_bounds__(256, 2) void gemm_kernel(
    const float* __restrict__ A, const float* __restrict__ B,
    const float* __restrict__ bias, float* __restrict__ C,
    int Mdim, int Ndim, int Kdim)
{
    __shared__ float As[16][128];
    __shared__ float Bs[16][132];
    const int tid = threadIdx.x;
    const int tx = tid & 15, ty = tid >> 4;
    const int m0 = blockIdx.y * 128, n0 = blockIdx.x * 128;
    float acc[8][8];
#pragma unroll
    for (int i = 0; i < 8; i++)
#pragma unroll
        for (int j = 0; j < 8; j++) acc[i][j] = 0.f;
    for (int k0 = 0; k0 < Kdim; k0 += 16) {
#pragma unroll
        for (int s = 0; s < 2; s++) {
            int f4 = tid + 256 * s;
            int row = f4 >> 2, kq = (f4 & 3) * 4;
            float4 av = *(const float4*)&A[(size_t)(m0 + row) * Kdim + k0 + kq];
            As[kq + 0][row] = av.x; As[kq + 1][row] = av.y;
            As[kq + 2][row] = av.z; As[kq + 3][row] = av.w;
        }
#pragma unroll
        for (int s = 0; s < 2; s++) {
            int f4 = tid + 256 * s;
            int row = f4 >> 5, nq = (f4 & 31) * 4;
            *(float4*)&Bs[row][nq] = *(const float4*)&B[(size_t)(k0 + row) * Ndim + n0 + nq];
        }
        __syncthreads();
#pragma unroll
        for (int k = 0; k < 16; k++) {
            float a[8], b[8];
            *(float4*)&a[0] = *(const float4*)&As[k][ty * 8];
            *(float4*)&a[4] = *(const float4*)&As[k][ty * 8 + 4];
            *(float4*)&b[0] = *(const float4*)&Bs[k][tx * 8];
            *(float4*)&b[4] = *(const float4*)&Bs[k][tx * 8 + 4];
#pragma unroll
            for (int i = 0; i < 8; i++)
#pragma unroll
                for (int j = 0; j < 8; j++) acc[i][j] += a[i] * b[j];
        }
        __syncthreads();
    }
#pragma unroll
    for (int i = 0; i < 8; i++) {
        int row = m0 + ty * 8 + i;
#pragma unroll
        for (int j = 0; j < 8; j++) {
            int col = n0 + tx * 8 + j;
            C[(size_t)row * Ndim + col] = acc[i][j] + bias[col];
        }
    }
}

// ---------------------------------------------------------------------------
// Weight transpose: out[N,K] = in[K,N]^T
// ---------------------------------------------------------------------------
__global__ void wtrans_kernel(const float* __restrict__ in, float* __restrict__ out,
                              int R, int Ccols)
{
    __shared__ float tl[32][33];
    int c0 = blockIdx.x * 32, r0 = blockIdx.y * 32;
#pragma unroll
    for (int i = 0; i < 32; i += 8)
        tl[threadIdx.y + i][threadIdx.x] = in[(size_t)(r0 + threadIdx.y + i) * Ccols + c0 + threadIdx.x];
    __syncthreads();
#pragma unroll
    for (int i = 0; i < 32; i += 8)
        out[(size_t)(c0 + threadIdx.y + i) * R + r0 + threadIdx.x] = tl[threadIdx.x][threadIdx.y + i];
}

// ---------------------------------------------------------------------------
// Fused attention per (batch, head)
// ---------------------------------------------------------------------------
__global__ __launch_bounds__(256) void attn_kernel(
    const float* __restrict__ Q, const float* __restrict__ K,
    const float* __restrict__ V, float* __restrict__ scores,
    float* __restrict__ O, float* __restrict__ attn_out, int has_prev)
{
    extern __shared__ float sm[];
    float* Qs = sm;
    float* Ks = sm + 4096;
    float* Ss = sm + 8256;

    const int bh = blockIdx.x;
    const int bv = bh / NHEAD, h = bh % NHEAD;
    const int row0 = bv * LSEQ, c0 = h * 64;
    const int t = threadIdx.x;
    const size_t sb = (size_t)bh * 4096;

#pragma unroll
    for (int s = 0; s < 16; s++) {
        int e = t + 256 * s;
        int i = e >> 6, kk = e & 63;
        Qs[i * 64 + kk] = Q[(size_t)(row0 + i) * DM + c0 + kk];
        Ks[i * 65 + kk] = K[(size_t)(row0 + i) * DM + c0 + kk];
    }
    __syncthreads();

#pragma unroll 2
    for (int s = 0; s < 16; s++) {
        int e = t + 256 * s;
        int i = e >> 6, j = e & 63;
        float sum = 0.f;
#pragma unroll
        for (int kk = 0; kk < 64; kk++) sum += Qs[i * 64 + kk] * Ks[j * 65 + kk];
        float val = sum * 0.125f;
        if (has_prev) val += scores[sb + e];
        scores[sb + e] = val;
        Ss[e] = val;
    }
    __syncthreads();

    const int w = t >> 5, lane = t & 31;
#pragma unroll
    for (int p = 0; p < 8; p++) {
        int r = w * 8 + p;
        float v0 = Ss[r * 64 + lane], v1 = Ss[r * 64 + lane + 32];
        float mx = fmaxf(v0, v1);
#pragma unroll
        for (int off = 16; off > 0; off >>= 1)
            mx = fmaxf(mx, __shfl_xor_sync(0xffffffffu, mx, off));
        float e0 = __expf(v0 - mx), e1 = __expf(v1 - mx);
        float sumv = e0 + e1;
#pragma unroll
        for (int off = 16; off > 0; off >>= 1)
            sumv += __shfl_xor_sync(0xffffffffu, sumv, off);
        float inv = 1.0f / sumv;
        e0 *= inv; e1 *= inv;
        Ss[r * 64 + lane] = e0;
        Ss[r * 64 + lane + 32] = e1;
        if (attn_out) {
            attn_out[sb + r * 64 + lane] = e0;
            attn_out[sb + r * 64 + lane + 32] = e1;
        }
    }
    __syncthreads();

#pragma unroll
    for (int s = 0; s < 16; s++) {
        int e = t + 256 * s;
        int i = e >> 6, kk = e & 63;
        Ks[i * 65 + kk] = V[(size_t)(row0 + i) * DM + c0 + kk];
    }
    __syncthreads();

#pragma unroll 2
    for (int s = 0; s < 16; s++) {
        int e = t + 256 * s;
        int i = e >> 6, dk = e & 63;
        float sum = 0.f;
#pragma unroll
        for (int j = 0; j < 64; j++) sum += Ss[i * 64 + j] * Ks[j * 65 + dk];
        O[(size_t)(row0 + i) * DM + c0 + dk] = sum;
    }
}

// ---------------------------------------------------------------------------
// BatchNorm
// ---------------------------------------------------------------------------
__global__ void zero_stats_kernel(float* stats)
{
    int idx = blockIdx.x * 256 + threadIdx.x;
    if (idx < 2 * DM) stats[idx] = 0.f;
}

__global__ __launch_bounds__(256) void bn_add_stats_kernel(
    float* __restrict__ u, const float* __restrict__ t2, float* __restrict__ stats)
{
    const int c0 = threadIdx.x;
    float s0 = 0, s1 = 0, s2 = 0, q0 = 0, q1 = 0, q2 = 0;
    const int rbase = blockIdx.x * 128;
    for (int r = 0; r < 128; r++) {
        size_t base = (size_t)(rbase + r) * DM;
        float a0 = u[base + c0] + t2[base + c0];
        float a1 = u[base + c0 + 256] + t2[base + c0 + 256];
        float a2 = u[base + c0 + 512] + t2[base + c0 + 512];
        u[base + c0] = a0; u[base + c0 + 256] = a1; u[base + c0 + 512] = a2;
        s0 += a0; s1 += a1; s2 += a2;
        q0 += a0 * a0; q1 += a1 * a1; q2 += a2 * a2;
    }
    atomicAdd(&stats[c0], s0);
    atomicAdd(&stats[c0 + 256], s1);
    atomicAdd(&stats[c0 + 512], s2);
    atomicAdd(&stats[DM + c0], q0);
    atomicAdd(&stats[DM + c0 + 256], q1);
    atomicAdd(&stats[DM + c0 + 512], q2);
}

__global__ __launch_bounds__(256) void bn_norm_kernel(
    float* __restrict__ u, const float* __restrict__ stats,
    const float* __restrict__ g, const float* __restrict__ be)
{
    int idx = blockIdx.x * 256 + threadIdx.x;
    int c = idx % DM;
    const float invM = 1.0f / (float)MROWS;
    float mean = stats[c] * invM;
    float var = stats[DM + c] * invM - mean * mean;
    float iv = rsqrtf(var + 1e-5f);
    u[idx] = (u[idx] - mean) * iv * g[c] + be[c];
}

// ---------------------------------------------------------------------------
// Misc remap / transposes
// ---------------------------------------------------------------------------
__global__ __launch_bounds__(256) void remap_embed_kernel(
    const float* __restrict__ h, const float* __restrict__ Wpos, float* __restrict__ u)
{
    int idx = blockIdx.x * 256 + threadIdx.x;
    int ru = idx / DM, d = idx % DM;
    int bv = ru >> 6, n = ru & 63;
    int b = bv / 7, v = bv % 7;
    int rh = (b * 64 + n) * 7 + v;
    u[idx] = h[(size_t)rh * DM + d] + Wpos[n * DM + d];
}

__global__ void transpose_h_kernel(const float* __restrict__ h, float* __restrict__ out)
{
    __shared__ float tile[32][33];
    int bv = blockIdx.z, b = bv / 7, v = bv % 7;
    int d0 = blockIdx.x * 32, n0 = blockIdx.y * 32;
#pragma unroll
    for (int i = 0; i < 32; i += 8) {
        int n = n0 + threadIdx.y + i;
        int d = d0 + threadIdx.x;
        tile[threadIdx.y + i][threadIdx.x] = h[((size_t)(b * 64 + n) * 7 + v) * DM + d];
    }
    __syncthreads();
#pragma unroll
    for (int i = 0; i < 32; i += 8) {
        int d = d0 + threadIdx.y + i;
        int n = n0 + threadIdx.x;
        out[((size_t)bv * DM + d) * LSEQ + n] = tile[threadIdx.x][threadIdx.y + i];
    }
}

__global__ void transpose_z_kernel(const float* __restrict__ u, float* __restrict__ out)
{
    __shared__ float tile[32][33];
    int bv = blockIdx.z;
    int d0 = blockIdx.x * 32, n0 = blockIdx.y * 32;
#pragma unroll
    for (int i = 0; i < 32; i += 8) {
        int n = n0 + threadIdx.y + i;
        int d = d0 + threadIdx.x;
        tile[threadIdx.y + i][threadIdx.x] = u[(size_t)(bv * 64 + n) * DM + d];
    }
    __syncthreads();
#pragma unroll
    for (int i = 0; i < 32; i += 8) {
        int d = d0 + threadIdx.y + i;
        int n = n0 + threadIdx.x;
        out[((size_t)bv * DM + d) * LSEQ + n] = tile[threadIdx.x][threadIdx.y + i];
    }
}

// ---------------------------------------------------------------------------

extern "C" void kernel_launch(void* const* d_in, const int* in_sizes, int n_in,
                              void* d_out, int out_size)
{
    const float* x    = (const float*)d_in[0];
    const float* Wp   = (const float*)d_in[1];
    const float* bp   = (const float*)d_in[2];
    const float* Wpos = (const float*)d_in[3];
    const float* Wq   = (const float*)d_in[4];
    const float* bq   = (const float*)d_in[5];
    const float* Wk   = (const float*)d_in[6];
    const float* bk   = (const float*)d_in[7];
    const float* Wv   = (const float*)d_in[8];
    const float* bv_  = (const float*)d_in[9];
    const float* Wo   = (const float*)d_in[10];
    const float* bo   = (const float*)d_in[11];
    const float* g1   = (const float*)d_in[12];
    const float* be1  = (const float*)d_in[13];
    const float* W1   = (const float*)d_in[14];
    const float* b1   = (const float*)d_in[15];
    const float* W2   = (const float*)d_in[16];
    const float* b2   = (const float*)d_in[17];
    const float* g2   = (const float*)d_in[18];
    const float* be2  = (const float*)d_in[19];

    float* out      = (float*)d_out;
    float* out_z    = out;
    float* out_h    = out + OUTSZ;
    float* out_attn = out + 2 * (size_t)OUTSZ;

    float *u, *q, *k, *v, *t, *sc, *ff, *st;
    float *wqt, *wkt, *wvt, *wot, *w1t, *w2t;
    cudaGetSymbolAddress((void**)&u,  g_u);
    cudaGetSymbolAddress((void**)&q,  g_q);
    cudaGetSymbolAddress((void**)&k,  g_k);
    cudaGetSymbolAddress((void**)&v,  g_v);
    cudaGetSymbolAddress((void**)&t,  g_t);
    cudaGetSymbolAddress((void**)&sc, g_scores);
    cudaGetSymbolAddress((void**)&ff, g_ff);
    cudaGetSymbolAddress((void**)&st, g_stats);
    cudaGetSymbolAddress((void**)&wqt, g_wqt);
    cudaGetSymbolAddress((void**)&wkt, g_wkt);
    cudaGetSymbolAddress((void**)&wvt, g_wvt);
    cudaGetSymbolAddress((void**)&wot, g_wot);
    cudaGetSymbolAddress((void**)&w1t, g_w1t);
    cudaGetSymbolAddress((void**)&w2t, g_w2t);

    cudaFuncSetAttribute(attn_kernel, cudaFuncAttributeMaxDynamicSharedMemorySize, 49408);
    cudaFuncSetAttribute(mma_gemm<0>, cudaFuncAttributeMaxDynamicSharedMemorySize, MMA_SMEM);
    cudaFuncSetAttribute(mma_gemm<1>, cudaFuncAttributeMaxDynamicSharedMemorySize, MMA_SMEM);

    const dim3 blk(256);
    const int elemBlocks = (MROWS * DM) / 256;
    const dim3 tgrid(24, 2, BH);
    const dim3 tblk32(32, 8);
    const dim3 gD(DM / 128, MROWS / 128);   // (6, 224)
    const dim3 gF(DF / 128, MROWS / 128);   // (24, 224)

    // Transpose weights [K,N] -> [N,K]
    for (int l = 0; l < 3; l++) {
        dim3 gdd(DM / 32, DM / 32);
        wtrans_kernel<<<gdd, tblk32>>>(Wq + (size_t)l * DM * DM, wqt + (size_t)l * DM * DM, DM, DM);
        wtrans_kernel<<<gdd, tblk32>>>(Wk + (size_t)l * DM * DM, wkt + (size_t)l * DM * DM, DM, DM);
        wtrans_kernel<<<gdd, tblk32>>>(Wv + (size_t)l * DM * DM, wvt + (size_t)l * DM * DM, DM, DM);
        wtrans_kernel<<<gdd, tblk32>>>(Wo + (size_t)l * DM * DM, wot + (size_t)l * DM * DM, DM, DM);
        dim3 g1d(DF / 32, DM / 32);
        wtrans_kernel<<<g1d, tblk32>>>(W1 + (size_t)l * DM * DF, w1t + (size_t)l * DM * DF, DM, DF);
        dim3 g2d(DM / 32, DF / 32);
        wtrans_kernel<<<g2d, tblk32>>>(W2 + (size_t)l * DF * DM, w2t + (size_t)l * DF * DM, DF, DM);
    }

    // patch embedding (K=16, fp32)
    gemm_kernel<<<dim3(DM / 128, MROWS / 128), blk>>>(x, Wp, bp, t, MROWS, DM, 16);
    remap_embed_kernel<<<elemBlocks, blk>>>(t, Wpos, u);
    transpose_h_kernel<<<tgrid, tblk32>>>(t, out_h);

    for (int l = 0; l < 3; l++) {
        mma_gemm<0><<<gD, blk, MMA_SMEM>>>(u, wqt + (size_t)l * DM * DM, bq + l * DM, q, DM, DM);
        mma_gemm<0><<<gD, blk, MMA_SMEM>>>(u, wkt + (size_t)l * DM * DM, bk + l * DM, k, DM, DM);
        mma_gemm<0><<<gD, blk, MMA_SMEM>>>(u, wvt + (size_t)l * DM * DM, bv_ + l * DM, v, DM, DM);

        attn_kernel<<<BH * NHEAD, 256, 49408>>>(
            q, k, v, sc, q, (l == 2) ? out_attn : nullptr, (l > 0) ? 1 : 0);

        mma_gemm<0><<<gD, blk, MMA_SMEM>>>(q, wot + (size_t)l * DM * DM, bo + l * DM, t, DM, DM);

        zero_stats_kernel<<<6, 256>>>(st);
        bn_add_stats_kernel<<<MROWS / 128, 256>>>(u, t, st);
        bn_norm_kernel<<<elemBlocks, blk>>>(u, st, g1 + l * DM, be1 + l * DM);

        mma_gemm<1><<<gF, blk, MMA_SMEM>>>(u, w1t + (size_t)l * DM * DF, b1 + l * DF, ff, DF, DM);
        mma_gemm<0><<<gD, blk, MMA_SMEM>>>(ff, w2t + (size_t)l * DF * DM, b2 + l * DM, t, DM, DF);

        zero_stats_kernel<<<6, 256>>>(st);
        bn_add_stats_kernel<<<MROWS / 128, 256>>>(u, t, st);
        bn_norm_kernel<<<elemBlocks, blk>>>(u, st, g2 + l * DM, be2 + l * DM);
    }

    transpose_z_kernel<<<tgrid, tblk32>>>(u, out_z);
}

// round 4
// speedup vs baseline: 4.0575x; 2.4637x over previous
#include <cuda_runtime.h>
#include <cuda_fp16.h>
#include <math.h>
#include <stdint.h>

// ---------------------------------------------------------------------------
// RockTS encoder: BS=64, NP=64, NV=7, PL=16, DM=768, NH=12, DK=64, DF=3072, NL=3
// M = 28672 rows. Outputs: z | h_t | attn concatenated in d_out.
// R4: fp16 m16n8k16 mma.sync GEMMs, fp16 operands in gmem, cp.async pipeline.
// ---------------------------------------------------------------------------

#define MROWS 28672
#define DM    768
#define DF    3072
#define LSEQ  64
#define BH    448
#define NHEAD 12
#define OUTSZ 22020096

__device__ float  g_u[MROWS * DM];
__device__ __half g_uh[MROWS * DM];
__device__ float  g_q[MROWS * DM];
__device__ float  g_k[MROWS * DM];
__device__ float  g_v[MROWS * DM];
__device__ __half g_oh[MROWS * DM];
__device__ float  g_t[MROWS * DM];
__device__ __half g_ffh[MROWS * DF];
__device__ float  g_scores[BH * NHEAD * LSEQ * LSEQ];
__device__ float  g_stats[2 * DM];
__device__ __half g_wqt[3 * DM * DM];
__device__ __half g_wkt[3 * DM * DM];
__device__ __half g_wvt[3 * DM * DM];
__device__ __half g_wot[3 * DM * DM];
__device__ __half g_w1t[3 * DM * DF];
__device__ __half g_w2t[3 * DF * DM];

// ---------------------------------------------------------------------------
// fp16 MMA GEMM: C[M,N] = A[M,K] @ Bt[N,K]^T + bias, optional GELU,
// writes fp32 and/or fp16 outputs.
// BM=BN=128, BK=32, 8 warps (2m x 4n), warp tile 64x32, m16n8k16.
// Smem rows padded to 40 halfs (bank-conflict-free b32 fragment loads).
// ---------------------------------------------------------------------------
#define SROWH 40

__device__ __forceinline__ void cpasync16(void* smp, const void* gp) {
    uint32_t sa = (uint32_t)__cvta_generic_to_shared(smp);
    asm volatile("cp.async.cg.shared.global [%0], [%1], 16;" :: "r"(sa), "l"(gp));
}

template<int GELU_EPI, int WRITE_F, int WRITE_H>
__global__ __launch_bounds__(256, 2) void hgemm(
    const __half* __restrict__ A, const __half* __restrict__ Bt,
    const float* __restrict__ bias, float* __restrict__ Cf,
    __half* __restrict__ Ch, int N, int K)
{
    __shared__ __half smA[2][128 * SROWH];
    __shared__ __half smB[2][128 * SROWH];

    const int tid  = threadIdx.x;
    const int wid  = tid >> 5, lane = tid & 31;
    const int g    = lane >> 2, tig = lane & 3;
    const int wm   = (wid & 1) * 64;
    const int wn   = (wid >> 1) * 32;
    const int m0   = blockIdx.y * 128, n0 = blockIdx.x * 128;
    const int NK   = K >> 5;

    // chunk decomposition for cp.async: 512 16B-chunks per stage, 2/thread
    const int row_a = tid >> 1;              // rows 0..127 (2 threads/row? no:)
    // use: chunk c = tid + 256*r ; row = c>>2 ; cj = c&3
    float acc[16][4];
#pragma unroll
    for (int i = 0; i < 16; i++)
#pragma unroll
        for (int j = 0; j < 4; j++) acc[i][j] = 0.f;
    (void)row_a;

    // preload stage 0
    {
        const __half* Ab = A + (size_t)m0 * K;
        const __half* Bb = Bt + (size_t)n0 * K;
#pragma unroll
        for (int r = 0; r < 2; r++) {
            int c = tid + 256 * r;
            int row = c >> 2, cj = c & 3;
            cpasync16(&smA[0][row * SROWH + cj * 8], Ab + (size_t)row * K + cj * 8);
            cpasync16(&smB[0][row * SROWH + cj * 8], Bb + (size_t)row * K + cj * 8);
        }
        asm volatile("cp.async.commit_group;");
    }

    for (int it = 0; it < NK; it++) {
        const int s = it & 1;
        if (it + 1 < NK) {
            const __half* Ab = A + (size_t)m0 * K + (it + 1) * 32;
            const __half* Bb = Bt + (size_t)n0 * K + (it + 1) * 32;
#pragma unroll
            for (int r = 0; r < 2; r++) {
                int c = tid + 256 * r;
                int row = c >> 2, cj = c & 3;
                cpasync16(&smA[s ^ 1][row * SROWH + cj * 8], Ab + (size_t)row * K + cj * 8);
                cpasync16(&smB[s ^ 1][row * SROWH + cj * 8], Bb + (size_t)row * K + cj * 8);
            }
            asm volatile("cp.async.commit_group;");
            asm volatile("cp.async.wait_group 1;");
        } else {
            asm volatile("cp.async.wait_group 0;");
        }
        __syncthreads();

        const uint32_t* As32 = (const uint32_t*)smA[s];
        const uint32_t* Bs32 = (const uint32_t*)smB[s];
#pragma unroll
        for (int ks = 0; ks < 2; ks++) {
            const int kb = ks * 8 + tig;       // b32 index within padded row (20 b32/row)
            uint32_t a[4][4], b[4][2];
#pragma unroll
            for (int mt = 0; mt < 4; mt++) {
                int r0 = wm + mt * 16 + g;
                a[mt][0] = As32[r0 * 20 + kb];
                a[mt][1] = As32[(r0 + 8) * 20 + kb];
                a[mt][2] = As32[r0 * 20 + kb + 4];
                a[mt][3] = As32[(r0 + 8) * 20 + kb + 4];
            }
#pragma unroll
            for (int nt = 0; nt < 4; nt++) {
                int rn = wn + nt * 8 + g;
                b[nt][0] = Bs32[rn * 20 + kb];
                b[nt][1] = Bs32[rn * 20 + kb + 4];
            }
#pragma unroll
            for (int mt = 0; mt < 4; mt++)
#pragma unroll
                for (int nt = 0; nt < 4; nt++) {
                    float* c = acc[mt * 4 + nt];
                    asm volatile(
                        "mma.sync.aligned.m16n8k16.row.col.f32.f16.f16.f32 "
                        "{%0,%1,%2,%3}, {%4,%5,%6,%7}, {%8,%9}, {%0,%1,%2,%3};"
                        : "+f"(c[0]), "+f"(c[1]), "+f"(c[2]), "+f"(c[3])
                        : "r"(a[mt][0]), "r"(a[mt][1]), "r"(a[mt][2]), "r"(a[mt][3]),
                          "r"(b[nt][0]), "r"(b[nt][1]));
                }
        }
        __syncthreads();
    }

    // epilogue
#pragma unroll
    for (int mt = 0; mt < 4; mt++) {
#pragma unroll
        for (int nt = 0; nt < 4; nt++) {
            const float* c = acc[mt * 4 + nt];
            int col = n0 + wn + nt * 8 + 2 * tig;
            float b0 = bias[col], b1 = bias[col + 1];
            int r0 = m0 + wm + mt * 16 + g;
            float2 v0, v1;
            v0.x = c[0] + b0; v0.y = c[1] + b1;
            v1.x = c[2] + b0; v1.y = c[3] + b1;
            if (GELU_EPI) {
                v0.x = 0.5f * v0.x * (1.0f + erff(v0.x * 0.70710678118654752f));
                v0.y = 0.5f * v0.y * (1.0f + erff(v0.y * 0.70710678118654752f));
                v1.x = 0.5f * v1.x * (1.0f + erff(v1.x * 0.70710678118654752f));
                v1.y = 0.5f * v1.y * (1.0f + erff(v1.y * 0.70710678118654752f));
            }
            if (WRITE_F) {
                *(float2*)&Cf[(size_t)r0 * N + col] = v0;
                *(float2*)&Cf[(size_t)(r0 + 8) * N + col] = v1;
            }
            if (WRITE_H) {
                __half2 h0, h1;
                h0.x = __float2half(v0.x); h0.y = __float2half(v0.y);
                h1.x = __float2half(v1.x); h1.y = __float2half(v1.y);
                *(__half2*)&Ch[(size_t)r0 * N + col] = h0;
                *(__half2*)&Ch[(size_t)(r0 + 8) * N + col] = h1;
            }
        }
    }
}

// ---------------------------------------------------------------------------
// fp32 SGEMM (patch embed, K=16)
// ---------------------------------------------------------------------------
__global__ __launch_bounds__(256, 2) void gemm_kernel(
    const float* __restrict__ A, const float* __restrict__ B,
    const float* __restrict__ bias, float* __restrict__ C,
    int Mdim, int Ndim, int Kdim)
{
    __shared__ float As[16][128];
    __shared__ float Bs[16][132];
    const int tid = threadIdx.x;
    const int tx = tid & 15, ty = tid >> 4;
    const int m0 = blockIdx.y * 128, n0 = blockIdx.x * 128;
    float acc[8][8];
#pragma unroll
    for (int i = 0; i < 8; i++)
#pragma unroll
        for (int j = 0; j < 8; j++) acc[i][j] = 0.f;
    for (int k0 = 0; k0 < Kdim; k0 += 16) {
#pragma unroll
        for (int s = 0; s < 2; s++) {
            int f4 = tid + 256 * s;
            int row = f4 >> 2, kq = (f4 & 3) * 4;
            float4 av = *(const float4*)&A[(size_t)(m0 + row) * Kdim + k0 + kq];
            As[kq + 0][row] = av.x; As[kq + 1][row] = av.y;
            As[kq + 2][row] = av.z; As[kq + 3][row] = av.w;
        }
#pragma unroll
        for (int s = 0; s < 2; s++) {
            int f4 = tid + 256 * s;
            int row = f4 >> 5, nq = (f4 & 31) * 4;
            *(float4*)&Bs[row][nq] = *(const float4*)&B[(size_t)(k0 + row) * Ndim + n0 + nq];
        }
        __syncthreads();
#pragma unroll
        for (int k = 0; k < 16; k++) {
            float a[8], b[8];
            *(float4*)&a[0] = *(const float4*)&As[k][ty * 8];
            *(float4*)&a[4] = *(const float4*)&As[k][ty * 8 + 4];
            *(float4*)&b[0] = *(const float4*)&Bs[k][tx * 8];
            *(float4*)&b[4] = *(const float4*)&Bs[k][tx * 8 + 4];
#pragma unroll
            for (int i = 0; i < 8; i++)
#pragma unroll
                for (int j = 0; j < 8; j++) acc[i][j] += a[i] * b[j];
        }
        __syncthreads();
    }
#pragma unroll
    for (int i = 0; i < 8; i++) {
        int row = m0 + ty * 8 + i;
#pragma unroll
        for (int j = 0; j < 8; j++) {
            int col = n0 + tx * 8 + j;
            C[(size_t)row * Ndim + col] = acc[i][j] + bias[col];
        }
    }
}

// ---------------------------------------------------------------------------
// Weight transpose + fp16 convert: out[N,K] = half(in[K,N]^T)
// ---------------------------------------------------------------------------
__global__ void wtrans_kernel(const float* __restrict__ in, __half* __restrict__ out,
                              int R, int Ccols)
{
    __shared__ float tl[32][33];
    int c0 = blockIdx.x * 32, r0 = blockIdx.y * 32;
#pragma unroll
    for (int i = 0; i < 32; i += 8)
        tl[threadIdx.y + i][threadIdx.x] = in[(size_t)(r0 + threadIdx.y + i) * Ccols + c0 + threadIdx.x];
    __syncthreads();
#pragma unroll
    for (int i = 0; i < 32; i += 8)
        out[(size_t)(c0 + threadIdx.y + i) * R + r0 + threadIdx.x] =
            __float2half(tl[threadIdx.x][threadIdx.y + i]);
}

// ---------------------------------------------------------------------------
// Fused attention per (batch, head). O written as fp16.
// ---------------------------------------------------------------------------
__global__ __launch_bounds__(256) void attn_kernel(
    const float* __restrict__ Q, const float* __restrict__ K,
    const float* __restrict__ V, float* __restrict__ scores,
    __half* __restrict__ O, float* __restrict__ attn_out, int has_prev)
{
    extern __shared__ float sm[];
    float* Qs = sm;
    float* Ks = sm + 4096;
    float* Ss = sm + 8256;

    const int bh = blockIdx.x;
    const int bv = bh / NHEAD, h = bh % NHEAD;
    const int row0 = bv * LSEQ, c0 = h * 64;
    const int t = threadIdx.x;
    const size_t sb = (size_t)bh * 4096;

#pragma unroll
    for (int s = 0; s < 16; s++) {
        int e = t + 256 * s;
        int i = e >> 6, kk = e & 63;
        Qs[i * 64 + kk] = Q[(size_t)(row0 + i) * DM + c0 + kk];
        Ks[i * 65 + kk] = K[(size_t)(row0 + i) * DM + c0 + kk];
    }
    __syncthreads();

#pragma unroll 2
    for (int s = 0; s < 16; s++) {
        int e = t + 256 * s;
        int i = e >> 6, j = e & 63;
        float sum = 0.f;
#pragma unroll
        for (int kk = 0; kk < 64; kk++) sum += Qs[i * 64 + kk] * Ks[j * 65 + kk];
        float val = sum * 0.125f;
        if (has_prev) val += scores[sb + e];
        scores[sb + e] = val;
        Ss[e] = val;
    }
    __syncthreads();

    const int w = t >> 5, lane = t & 31;
#pragma unroll
    for (int p = 0; p < 8; p++) {
        int r = w * 8 + p;
        float v0 = Ss[r * 64 + lane], v1 = Ss[r * 64 + lane + 32];
        float mx = fmaxf(v0, v1);
#pragma unroll
        for (int off = 16; off > 0; off >>= 1)
            mx = fmaxf(mx, __shfl_xor_sync(0xffffffffu, mx, off));
        float e0 = __expf(v0 - mx), e1 = __expf(v1 - mx);
        float sumv = e0 + e1;
#pragma unroll
        for (int off = 16; off > 0; off >>= 1)
            sumv += __shfl_xor_sync(0xffffffffu, sumv, off);
        float inv = 1.0f / sumv;
        e0 *= inv; e1 *= inv;
        Ss[r * 64 + lane] = e0;
        Ss[r * 64 + lane + 32] = e1;
        if (attn_out) {
            attn_out[sb + r * 64 + lane] = e0;
            attn_out[sb + r * 64 + lane + 32] = e1;
        }
    }
    __syncthreads();

#pragma unroll
    for (int s = 0; s < 16; s++) {
        int e = t + 256 * s;
        int i = e >> 6, kk = e & 63;
        Ks[i * 65 + kk] = V[(size_t)(row0 + i) * DM + c0 + kk];
    }
    __syncthreads();

#pragma unroll 2
    for (int s = 0; s < 16; s++) {
        int e = t + 256 * s;
        int i = e >> 6, dk = e & 63;
        float sum = 0.f;
#pragma unroll
        for (int j = 0; j < 64; j++) sum += Ss[i * 64 + j] * Ks[j * 65 + dk];
        O[(size_t)(row0 + i) * DM + c0 + dk] = __float2half(sum);
    }
}

// ---------------------------------------------------------------------------
// BatchNorm
// ---------------------------------------------------------------------------
__global__ void zero_stats_kernel(float* stats)
{
    int idx = blockIdx.x * 256 + threadIdx.x;
    if (idx < 2 * DM) stats[idx] = 0.f;
}

__global__ __launch_bounds__(256) void bn_add_stats_kernel(
    float* __restrict__ u, const float* __restrict__ t2, float* __restrict__ stats)
{
    const int c0 = threadIdx.x;
    float s0 = 0, s1 = 0, s2 = 0, q0 = 0, q1 = 0, q2 = 0;
    const int rbase = blockIdx.x * 128;
    for (int r = 0; r < 128; r++) {
        size_t base = (size_t)(rbase + r) * DM;
        float a0 = u[base + c0] + t2[base + c0];
        float a1 = u[base + c0 + 256] + t2[base + c0 + 256];
        float a2 = u[base + c0 + 512] + t2[base + c0 + 512];
        u[base + c0] = a0; u[base + c0 + 256] = a1; u[base + c0 + 512] = a2;
        s0 += a0; s1 += a1; s2 += a2;
        q0 += a0 * a0; q1 += a1 * a1; q2 += a2 * a2;
    }
    atomicAdd(&stats[c0], s0);
    atomicAdd(&stats[c0 + 256], s1);
    atomicAdd(&stats[c0 + 512], s2);
    atomicAdd(&stats[DM + c0], q0);
    atomicAdd(&stats[DM + c0 + 256], q1);
    atomicAdd(&stats[DM + c0 + 512], q2);
}

__global__ __launch_bounds__(256) void bn_norm_kernel(
    float* __restrict__ u, __half* __restrict__ uh, const float* __restrict__ stats,
    const float* __restrict__ g, const float* __restrict__ be)
{
    int idx = blockIdx.x * 256 + threadIdx.x;
    int c = idx % DM;
    const float invM = 1.0f / (float)MROWS;
    float mean = stats[c] * invM;
    float var = stats[DM + c] * invM - mean * mean;
    float iv = rsqrtf(var + 1e-5f);
    float val = (u[idx] - mean) * iv * g[c] + be[c];
    u[idx] = val;
    uh[idx] = __float2half(val);
}

// ---------------------------------------------------------------------------
// Misc remap / transposes
// ---------------------------------------------------------------------------
__global__ __launch_bounds__(256) void remap_embed_kernel(
    const float* __restrict__ h, const float* __restrict__ Wpos,
    float* __restrict__ u, __half* __restrict__ uh)
{
    int idx = blockIdx.x * 256 + threadIdx.x;
    int ru = idx / DM, d = idx % DM;
    int bv = ru >> 6, n = ru & 63;
    int b = bv / 7, v = bv % 7;
    int rh = (b * 64 + n) * 7 + v;
    float val = h[(size_t)rh * DM + d] + Wpos[n * DM + d];
    u[idx] = val;
    uh[idx] = __float2half(val);
}

__global__ void transpose_h_kernel(const float* __restrict__ h, float* __restrict__ out)
{
    __shared__ float tile[32][33];
    int bv = blockIdx.z, b = bv / 7, v = bv % 7;
    int d0 = blockIdx.x * 32, n0 = blockIdx.y * 32;
#pragma unroll
    for (int i = 0; i < 32; i += 8) {
        int n = n0 + threadIdx.y + i;
        int d = d0 + threadIdx.x;
        tile[threadIdx.y + i][threadIdx.x] = h[((size_t)(b * 64 + n) * 7 + v) * DM + d];
    }
    __syncthreads();
#pragma unroll
    for (int i = 0; i < 32; i += 8) {
        int d = d0 + threadIdx.y + i;
        int n = n0 + threadIdx.x;
        out[((size_t)bv * DM + d) * LSEQ + n] = tile[threadIdx.x][threadIdx.y + i];
    }
}

__global__ void transpose_z_kernel(const float* __restrict__ u, float* __restrict__ out)
{
    __shared__ float tile[32][33];
    int bv = blockIdx.z;
    int d0 = blockIdx.x * 32, n0 = blockIdx.y * 32;
#pragma unroll
    for (int i = 0; i < 32; i += 8) {
        int n = n0 + threadIdx.y + i;
        int d = d0 + threadIdx.x;
        tile[threadIdx.y + i][threadIdx.x] = u[(size_t)(bv * 64 + n) * DM + d];
    }
    __syncthreads();
#pragma unroll
    for (int i = 0; i < 32; i += 8) {
        int d = d0 + threadIdx.y + i;
        int n = n0 + threadIdx.x;
        out[((size_t)bv * DM + d) * LSEQ + n] = tile[threadIdx.x][threadIdx.y + i];
    }
}

// ---------------------------------------------------------------------------

extern "C" void kernel_launch(void* const* d_in, const int* in_sizes, int n_in,
                              void* d_out, int out_size)
{
    const float* x    = (const float*)d_in[0];
    const float* Wp   = (const float*)d_in[1];
    const float* bp   = (const float*)d_in[2];
    const float* Wpos = (const float*)d_in[3];
    const float* Wq   = (const float*)d_in[4];
    const float* bq   = (const float*)d_in[5];
    const float* Wk   = (const float*)d_in[6];
    const float* bk   = (const float*)d_in[7];
    const float* Wv   = (const float*)d_in[8];
    const float* bv_  = (const float*)d_in[9];
    const float* Wo   = (const float*)d_in[10];
    const float* bo   = (const float*)d_in[11];
    const float* g1   = (const float*)d_in[12];
    const float* be1  = (const float*)d_in[13];
    const float* W1   = (const float*)d_in[14];
    const float* b1   = (const float*)d_in[15];
    const float* W2   = (const float*)d_in[16];
    const float* b2   = (const float*)d_in[17];
    const float* g2   = (const float*)d_in[18];
    const float* be2  = (const float*)d_in[19];

    float* out      = (float*)d_out;
    float* out_z    = out;
    float* out_h    = out + OUTSZ;
    float* out_attn = out + 2 * (size_t)OUTSZ;

    float *u, *q, *k, *v, *t, *sc, *st;
    __half *uh, *oh, *ffh, *wqt, *wkt, *wvt, *wot, *w1t, *w2t;
    cudaGetSymbolAddress((void**)&u,  g_u);
    cudaGetSymbolAddress((void**)&uh, g_uh);
    cudaGetSymbolAddress((void**)&q,  g_q);
    cudaGetSymbolAddress((void**)&k,  g_k);
    cudaGetSymbolAddress((void**)&v,  g_v);
    cudaGetSymbolAddress((void**)&oh, g_oh);
    cudaGetSymbolAddress((void**)&t,  g_t);
    cudaGetSymbolAddress((void**)&ffh, g_ffh);
    cudaGetSymbolAddress((void**)&sc, g_scores);
    cudaGetSymbolAddress((void**)&st, g_stats);
    cudaGetSymbolAddress((void**)&wqt, g_wqt);
    cudaGetSymbolAddress((void**)&wkt, g_wkt);
    cudaGetSymbolAddress((void**)&wvt, g_wvt);
    cudaGetSymbolAddress((void**)&wot, g_wot);
    cudaGetSymbolAddress((void**)&w1t, g_w1t);
    cudaGetSymbolAddress((void**)&w2t, g_w2t);

    cudaFuncSetAttribute(attn_kernel, cudaFuncAttributeMaxDynamicSharedMemorySize, 49408);

    const dim3 blk(256);
    const int elemBlocks = (MROWS * DM) / 256;
    const dim3 tgrid(24, 2, BH);
    const dim3 tblk32(32, 8);
    const dim3 gD(DM / 128, MROWS / 128);   // (6, 224)
    const dim3 gF(DF / 128, MROWS / 128);   // (24, 224)

    // Transpose + fp16-convert weights [K,N] -> [N,K]
    for (int l = 0; l < 3; l++) {
        dim3 gdd(DM / 32, DM / 32);
        wtrans_kernel<<<gdd, tblk32>>>(Wq + (size_t)l * DM * DM, wqt + (size_t)l * DM * DM, DM, DM);
        wtrans_kernel<<<gdd, tblk32>>>(Wk + (size_t)l * DM * DM, wkt + (size_t)l * DM * DM, DM, DM);
        wtrans_kernel<<<gdd, tblk32>>>(Wv + (size_t)l * DM * DM, wvt + (size_t)l * DM * DM, DM, DM);
        wtrans_kernel<<<gdd, tblk32>>>(Wo + (size_t)l * DM * DM, wot + (size_t)l * DM * DM, DM, DM);
        dim3 g1d(DF / 32, DM / 32);
        wtrans_kernel<<<g1d, tblk32>>>(W1 + (size_t)l * DM * DF, w1t + (size_t)l * DM * DF, DM, DF);
        dim3 g2d(DM / 32, DF / 32);
        wtrans_kernel<<<g2d, tblk32>>>(W2 + (size_t)l * DF * DM, w2t + (size_t)l * DF * DM, DF, DM);
    }

    // patch embedding (K=16, fp32)
    gemm_kernel<<<dim3(DM / 128, MROWS / 128), blk>>>(x, Wp, bp, t, MROWS, DM, 16);
    remap_embed_kernel<<<elemBlocks, blk>>>(t, Wpos, u, uh);
    transpose_h_kernel<<<tgrid, tblk32>>>(t, out_h);

    for (int l = 0; l < 3; l++) {
        hgemm<0, 1, 0><<<gD, blk>>>(uh, wqt + (size_t)l * DM * DM, bq + l * DM, q, nullptr, DM, DM);
        hgemm<0, 1, 0><<<gD, blk>>>(uh, wkt + (size_t)l * DM * DM, bk + l * DM, k, nullptr, DM, DM);
        hgemm<0, 1, 0><<<gD, blk>>>(uh, wvt + (size_t)l * DM * DM, bv_ + l * DM, v, nullptr, DM, DM);

        attn_kernel<<<BH * NHEAD, 256, 49408>>>(
            q, k, v, sc, oh, (l == 2) ? out_attn : nullptr, (l > 0) ? 1 : 0);

        hgemm<0, 1, 0><<<gD, blk>>>(oh, wot + (size_t)l * DM * DM, bo + l * DM, t, nullptr, DM, DM);

        zero_stats_kernel<<<6, 256>>>(st);
        bn_add_stats_kernel<<<MROWS / 128, 256>>>(u, t, st);
        bn_norm_kernel<<<elemBlocks, blk>>>(u, uh, st, g1 + l * DM, be1 + l * DM);

        hgemm<1, 0, 1><<<gF, blk>>>(uh, w1t + (size_t)l * DM * DF, b1 + l * DF, nullptr, ffh, DF, DM);
        hgemm<0, 1, 0><<<gD, blk>>>(ffh, w2t + (size_t)l * DF * DM, b2 + l * DM, t, nullptr, DM, DF);

        zero_stats_kernel<<<6, 256>>>(st);
        bn_add_stats_kernel<<<MROWS / 128, 256>>>(u, t, st);
        bn_norm_kernel<<<elemBlocks, blk>>>(u, uh, st, g2 + l * DM, be2 + l * DM);
    }

    transpose_z_kernel<<<tgrid, tblk32>>>(u, out_z);
}

// round 5
// speedup vs baseline: 4.7308x; 1.1659x over previous
#include <cuda_runtime.h>
#include <cuda_fp16.h>
#include <math.h>
#include <stdint.h>

// ---------------------------------------------------------------------------
// RockTS encoder: BS=64, NP=64, NV=7, PL=16, DM=768, NH=12, DK=64, DF=3072, NL=3
// M = 28672 rows. Outputs: z | h_t | attn concatenated in d_out.
// R5: ldmatrix fragment loads in hgemm; register-blocked fp32 attention.
// ---------------------------------------------------------------------------

#define MROWS 28672
#define DM    768
#define DF    3072
#define LSEQ  64
#define BH    448
#define NHEAD 12
#define OUTSZ 22020096

__device__ float  g_u[MROWS * DM];
__device__ __half g_uh[MROWS * DM];
__device__ float  g_q[MROWS * DM];
__device__ float  g_k[MROWS * DM];
__device__ float  g_v[MROWS * DM];
__device__ __half g_oh[MROWS * DM];
__device__ float  g_t[MROWS * DM];
__device__ __half g_ffh[MROWS * DF];
__device__ float  g_scores[BH * NHEAD * LSEQ * LSEQ];
__device__ float  g_stats[2 * DM];
__device__ __half g_wqt[3 * DM * DM];
__device__ __half g_wkt[3 * DM * DM];
__device__ __half g_wvt[3 * DM * DM];
__device__ __half g_wot[3 * DM * DM];
__device__ __half g_w1t[3 * DM * DF];
__device__ __half g_w2t[3 * DF * DM];

// ---------------------------------------------------------------------------
// fp16 MMA GEMM with ldmatrix: C[M,N] = A[M,K] @ Bt[N,K]^T + bias
// BM=BN=128, BK=32, 8 warps (2m x 4n), warp tile 64x32, m16n8k16.
// ---------------------------------------------------------------------------
#define SROWH 40
#define STAGE_BYTES (128 * SROWH * 2)

__device__ __forceinline__ void cpasync16(void* smp, const void* gp) {
    uint32_t sa = (uint32_t)__cvta_generic_to_shared(smp);
    asm volatile("cp.async.cg.shared.global [%0], [%1], 16;" :: "r"(sa), "l"(gp));
}

template<int GELU_EPI, int WRITE_F, int WRITE_H>
__global__ __launch_bounds__(256, 2) void hgemm(
    const __half* __restrict__ A, const __half* __restrict__ Bt,
    const float* __restrict__ bias, float* __restrict__ Cf,
    __half* __restrict__ Ch, int N, int K)
{
    __shared__ __half smA[2][128 * SROWH];
    __shared__ __half smB[2][128 * SROWH];

    const int tid  = threadIdx.x;
    const int wid  = tid >> 5, lane = tid & 31;
    const int g    = lane >> 2, tig = lane & 3;
    const int wm   = (wid & 1) * 64;
    const int wn   = (wid >> 1) * 32;
    const int m0   = blockIdx.y * 128, n0 = blockIdx.x * 128;
    const int NK   = K >> 5;

    // ldmatrix lane addressing
    const int arow  = lane & 15;               // A: row within 16-row tile
    const int akoff = (lane & 16) >> 1;        // A: +8 halfs for k8-15 matrices
    const int nrow  = ((lane & 16) >> 1) + (lane & 7);  // B: n row
    const int bkoff = lane & 8;                // B: +8 halfs for b1 matrices
    const uint32_t aBase = (uint32_t)__cvta_generic_to_shared(smA)
                         + ((wm + arow) * SROWH + akoff) * 2;
    const uint32_t bBase = (uint32_t)__cvta_generic_to_shared(smB)
                         + ((wn + nrow) * SROWH + bkoff) * 2;

    float acc[16][4];
#pragma unroll
    for (int i = 0; i < 16; i++)
#pragma unroll
        for (int j = 0; j < 4; j++) acc[i][j] = 0.f;

    // preload stage 0
    {
        const __half* Ab = A + (size_t)m0 * K;
        const __half* Bb = Bt + (size_t)n0 * K;
#pragma unroll
        for (int r = 0; r < 2; r++) {
            int c = tid + 256 * r;
            int row = c >> 2, cj = c & 3;
            cpasync16(&smA[0][row * SROWH + cj * 8], Ab + (size_t)row * K + cj * 8);
            cpasync16(&smB[0][row * SROWH + cj * 8], Bb + (size_t)row * K + cj * 8);
        }
        asm volatile("cp.async.commit_group;");
    }

    for (int it = 0; it < NK; it++) {
        const int s = it & 1;
        if (it + 1 < NK) {
            const __half* Ab = A + (size_t)m0 * K + (it + 1) * 32;
            const __half* Bb = Bt + (size_t)n0 * K + (it + 1) * 32;
#pragma unroll
            for (int r = 0; r < 2; r++) {
                int c = tid + 256 * r;
                int row = c >> 2, cj = c & 3;
                cpasync16(&smA[s ^ 1][row * SROWH + cj * 8], Ab + (size_t)row * K + cj * 8);
                cpasync16(&smB[s ^ 1][row * SROWH + cj * 8], Bb + (size_t)row * K + cj * 8);
            }
            asm volatile("cp.async.commit_group;");
            asm volatile("cp.async.wait_group 1;");
        } else {
            asm volatile("cp.async.wait_group 0;");
        }
        __syncthreads();

        const uint32_t aS = aBase + s * STAGE_BYTES;
        const uint32_t bS = bBase + s * STAGE_BYTES;
#pragma unroll
        for (int ks = 0; ks < 2; ks++) {
            uint32_t a[4][4], b[4][2];
#pragma unroll
            for (int mt = 0; mt < 4; mt++) {
                uint32_t ad = aS + mt * (16 * SROWH * 2) + ks * 32;
                asm volatile("ldmatrix.sync.aligned.m8n8.x4.shared.b16 {%0,%1,%2,%3}, [%4];"
                             : "=r"(a[mt][0]), "=r"(a[mt][1]), "=r"(a[mt][2]), "=r"(a[mt][3])
                             : "r"(ad));
            }
#pragma unroll
            for (int p = 0; p < 2; p++) {
                uint32_t bd = bS + p * (16 * SROWH * 2) + ks * 32;
                asm volatile("ldmatrix.sync.aligned.m8n8.x4.shared.b16 {%0,%1,%2,%3}, [%4];"
                             : "=r"(b[2 * p][0]), "=r"(b[2 * p][1]),
                               "=r"(b[2 * p + 1][0]), "=r"(b[2 * p + 1][1])
                             : "r"(bd));
            }
#pragma unroll
            for (int mt = 0; mt < 4; mt++)
#pragma unroll
                for (int nt = 0; nt < 4; nt++) {
                    float* c = acc[mt * 4 + nt];
                    asm volatile(
                        "mma.sync.aligned.m16n8k16.row.col.f32.f16.f16.f32 "
                        "{%0,%1,%2,%3}, {%4,%5,%6,%7}, {%8,%9}, {%0,%1,%2,%3};"
                        : "+f"(c[0]), "+f"(c[1]), "+f"(c[2]), "+f"(c[3])
                        : "r"(a[mt][0]), "r"(a[mt][1]), "r"(a[mt][2]), "r"(a[mt][3]),
                          "r"(b[nt][0]), "r"(b[nt][1]));
                }
        }
        __syncthreads();
    }

    // epilogue
#pragma unroll
    for (int mt = 0; mt < 4; mt++) {
#pragma unroll
        for (int nt = 0; nt < 4; nt++) {
            const float* c = acc[mt * 4 + nt];
            int col = n0 + wn + nt * 8 + 2 * tig;
            float b0 = bias[col], b1 = bias[col + 1];
            int r0 = m0 + wm + mt * 16 + g;
            float2 v0, v1;
            v0.x = c[0] + b0; v0.y = c[1] + b1;
            v1.x = c[2] + b0; v1.y = c[3] + b1;
            if (GELU_EPI) {
                v0.x = 0.5f * v0.x * (1.0f + erff(v0.x * 0.70710678118654752f));
                v0.y = 0.5f * v0.y * (1.0f + erff(v0.y * 0.70710678118654752f));
                v1.x = 0.5f * v1.x * (1.0f + erff(v1.x * 0.70710678118654752f));
                v1.y = 0.5f * v1.y * (1.0f + erff(v1.y * 0.70710678118654752f));
            }
            if (WRITE_F) {
                *(float2*)&Cf[(size_t)r0 * N + col] = v0;
                *(float2*)&Cf[(size_t)(r0 + 8) * N + col] = v1;
            }
            if (WRITE_H) {
                __half2 h0, h1;
                h0.x = __float2half(v0.x); h0.y = __float2half(v0.y);
                h1.x = __float2half(v1.x); h1.y = __float2half(v1.y);
                *(__half2*)&Ch[(size_t)r0 * N + col] = h0;
                *(__half2*)&Ch[(size_t)(r0 + 8) * N + col] = h1;
            }
        }
    }
}

// ---------------------------------------------------------------------------
// fp32 SGEMM (patch embed, K=16)
// ---------------------------------------------------------------------------
__global__ __launch_bounds__(256, 2) void gemm_kernel(
    const float* __restrict__ A, const float* __restrict__ B,
    const float* __restrict__ bias, float* __restrict__ C,
    int Mdim, int Ndim, int Kdim)
{
    __shared__ float As[16][128];
    __shared__ float Bs[16][132];
    const int tid = threadIdx.x;
    const int tx = tid & 15, ty = tid >> 4;
    const int m0 = blockIdx.y * 128, n0 = blockIdx.x * 128;
    float acc[8][8];
#pragma unroll
    for (int i = 0; i < 8; i++)
#pragma unroll
        for (int j = 0; j < 8; j++) acc[i][j] = 0.f;
    for (int k0 = 0; k0 < Kdim; k0 += 16) {
#pragma unroll
        for (int s = 0; s < 2; s++) {
            int f4 = tid + 256 * s;
            int row = f4 >> 2, kq = (f4 & 3) * 4;
            float4 av = *(const float4*)&A[(size_t)(m0 + row) * Kdim + k0 + kq];
            As[kq + 0][row] = av.x; As[kq + 1][row] = av.y;
            As[kq + 2][row] = av.z; As[kq + 3][row] = av.w;
        }
#pragma unroll
        for (int s = 0; s < 2; s++) {
            int f4 = tid + 256 * s;
            int row = f4 >> 5, nq = (f4 & 31) * 4;
            *(float4*)&Bs[row][nq] = *(const float4*)&B[(size_t)(k0 + row) * Ndim + n0 + nq];
        }
        __syncthreads();
#pragma unroll
        for (int k = 0; k < 16; k++) {
            float a[8], b[8];
            *(float4*)&a[0] = *(const float4*)&As[k][ty * 8];
            *(float4*)&a[4] = *(const float4*)&As[k][ty * 8 + 4];
            *(float4*)&b[0] = *(const float4*)&Bs[k][tx * 8];
            *(float4*)&b[4] = *(const float4*)&Bs[k][tx * 8 + 4];
#pragma unroll
            for (int i = 0; i < 8; i++)
#pragma unroll
                for (int j = 0; j < 8; j++) acc[i][j] += a[i] * b[j];
        }
        __syncthreads();
    }
#pragma unroll
    for (int i = 0; i < 8; i++) {
        int row = m0 + ty * 8 + i;
#pragma unroll
        for (int j = 0; j < 8; j++) {
            int col = n0 + tx * 8 + j;
            C[(size_t)row * Ndim + col] = acc[i][j] + bias[col];
        }
    }
}

// ---------------------------------------------------------------------------
// Weight transpose + fp16 convert: out[N,K] = half(in[K,N]^T)
// ---------------------------------------------------------------------------
__global__ void wtrans_kernel(const float* __restrict__ in, __half* __restrict__ out,
                              int R, int Ccols)
{
    __shared__ float tl[32][33];
    int c0 = blockIdx.x * 32, r0 = blockIdx.y * 32;
#pragma unroll
    for (int i = 0; i < 32; i += 8)
        tl[threadIdx.y + i][threadIdx.x] = in[(size_t)(r0 + threadIdx.y + i) * Ccols + c0 + threadIdx.x];
    __syncthreads();
#pragma unroll
    for (int i = 0; i < 32; i += 8)
        out[(size_t)(c0 + threadIdx.y + i) * R + r0 + threadIdx.x] =
            __float2half(tl[threadIdx.x][threadIdx.y + i]);
}

// ---------------------------------------------------------------------------
// Fused attention per (batch, head), register-blocked 4x4 per thread.
// smem: Qs 64*65 | Ks/Vs 64*65 | Ss 64*65 = 49920 B
// ---------------------------------------------------------------------------
__global__ __launch_bounds__(256) void attn_kernel(
    const float* __restrict__ Q, const float* __restrict__ K,
    const float* __restrict__ V, float* __restrict__ scores,
    __half* __restrict__ O, float* __restrict__ attn_out, int has_prev)
{
    extern __shared__ float sm[];
    float* Qs = sm;            // 64*65
    float* Ks = sm + 4160;     // 64*65 (reused for V)
    float* Ss = sm + 8320;     // 64*65

    const int bh = blockIdx.x;
    const int bv = bh / NHEAD, h = bh % NHEAD;
    const int row0 = bv * LSEQ, c0 = h * 64;
    const int t = threadIdx.x;
    const size_t sb = (size_t)bh * 4096;

    // load Q, K
#pragma unroll
    for (int s = 0; s < 16; s++) {
        int e = t + 256 * s;
        int i = e >> 6, kk = e & 63;
        Qs[i * 65 + kk] = Q[(size_t)(row0 + i) * DM + c0 + kk];
        Ks[i * 65 + kk] = K[(size_t)(row0 + i) * DM + c0 + kk];
    }
    __syncthreads();

    // QK^T: thread tile rows i0..i0+3, cols jc = (t&15) + 16*b
    const int i0 = (t >> 4) * 4;
    const int jc = t & 15;
    float acc[4][4];
#pragma unroll
    for (int a = 0; a < 4; a++)
#pragma unroll
        for (int b = 0; b < 4; b++) acc[a][b] = 0.f;

    for (int kk = 0; kk < 64; kk++) {
        float qa[4], kb[4];
#pragma unroll
        for (int a = 0; a < 4; a++) qa[a] = Qs[(i0 + a) * 65 + kk];
#pragma unroll
        for (int b = 0; b < 4; b++) kb[b] = Ks[(jc + 16 * b) * 65 + kk];
#pragma unroll
        for (int a = 0; a < 4; a++)
#pragma unroll
            for (int b = 0; b < 4; b++) acc[a][b] += qa[a] * kb[b];
    }

#pragma unroll
    for (int a = 0; a < 4; a++) {
#pragma unroll
        for (int b = 0; b < 4; b++) {
            int i = i0 + a, j = jc + 16 * b;
            float val = acc[a][b] * 0.125f;
            if (has_prev) val += scores[sb + i * 64 + j];
            scores[sb + i * 64 + j] = val;
            Ss[i * 65 + j] = val;
        }
    }
    __syncthreads();

    // softmax rows (8 warps x 8 rows, 2 cols/lane)
    const int w = t >> 5, lane = t & 31;
#pragma unroll
    for (int p = 0; p < 8; p++) {
        int r = w * 8 + p;
        float v0 = Ss[r * 65 + lane], v1 = Ss[r * 65 + lane + 32];
        float mx = fmaxf(v0, v1);
#pragma unroll
        for (int off = 16; off > 0; off >>= 1)
            mx = fmaxf(mx, __shfl_xor_sync(0xffffffffu, mx, off));
        float e0 = __expf(v0 - mx), e1 = __expf(v1 - mx);
        float sumv = e0 + e1;
#pragma unroll
        for (int off = 16; off > 0; off >>= 1)
            sumv += __shfl_xor_sync(0xffffffffu, sumv, off);
        float inv = 1.0f / sumv;
        e0 *= inv; e1 *= inv;
        Ss[r * 65 + lane] = e0;
        Ss[r * 65 + lane + 32] = e1;
        if (attn_out) {
            attn_out[sb + r * 64 + lane] = e0;
            attn_out[sb + r * 64 + lane + 32] = e1;
        }
    }
    __syncthreads();

    // V into Ks
#pragma unroll
    for (int s = 0; s < 16; s++) {
        int e = t + 256 * s;
        int i = e >> 6, kk = e & 63;
        Ks[i * 65 + kk] = V[(size_t)(row0 + i) * DM + c0 + kk];
    }
    __syncthreads();

    // P @ V: rows i0..i0+3, dk cols jc + 16*b
    float acc2[4][4];
#pragma unroll
    for (int a = 0; a < 4; a++)
#pragma unroll
        for (int b = 0; b < 4; b++) acc2[a][b] = 0.f;

    for (int j = 0; j < 64; j++) {
        float sa[4], vb[4];
#pragma unroll
        for (int a = 0; a < 4; a++) sa[a] = Ss[(i0 + a) * 65 + j];
#pragma unroll
        for (int b = 0; b < 4; b++) vb[b] = Ks[j * 65 + jc + 16 * b];
#pragma unroll
        for (int a = 0; a < 4; a++)
#pragma unroll
            for (int b = 0; b < 4; b++) acc2[a][b] += sa[a] * vb[b];
    }

#pragma unroll
    for (int a = 0; a < 4; a++)
#pragma unroll
        for (int b = 0; b < 4; b++)
            O[(size_t)(row0 + i0 + a) * DM + c0 + jc + 16 * b] = __float2half(acc2[a][b]);
}

// ---------------------------------------------------------------------------
// BatchNorm
// ---------------------------------------------------------------------------
__global__ void zero_stats_kernel(float* stats)
{
    int idx = blockIdx.x * 256 + threadIdx.x;
    if (idx < 2 * DM) stats[idx] = 0.f;
}

__global__ __launch_bounds__(256) void bn_add_stats_kernel(
    float* __restrict__ u, const float* __restrict__ t2, float* __restrict__ stats)
{
    const int c0 = threadIdx.x;
    float s0 = 0, s1 = 0, s2 = 0, q0 = 0, q1 = 0, q2 = 0;
    const int rbase = blockIdx.x * 128;
    for (int r = 0; r < 128; r++) {
        size_t base = (size_t)(rbase + r) * DM;
        float a0 = u[base + c0] + t2[base + c0];
        float a1 = u[base + c0 + 256] + t2[base + c0 + 256];
        float a2 = u[base + c0 + 512] + t2[base + c0 + 512];
        u[base + c0] = a0; u[base + c0 + 256] = a1; u[base + c0 + 512] = a2;
        s0 += a0; s1 += a1; s2 += a2;
        q0 += a0 * a0; q1 += a1 * a1; q2 += a2 * a2;
    }
    atomicAdd(&stats[c0], s0);
    atomicAdd(&stats[c0 + 256], s1);
    atomicAdd(&stats[c0 + 512], s2);
    atomicAdd(&stats[DM + c0], q0);
    atomicAdd(&stats[DM + c0 + 256], q1);
    atomicAdd(&stats[DM + c0 + 512], q2);
}

__global__ __launch_bounds__(256) void bn_norm_kernel(
    float* __restrict__ u, __half* __restrict__ uh, const float* __restrict__ stats,
    const float* __restrict__ g, const float* __restrict__ be)
{
    int idx = blockIdx.x * 256 + threadIdx.x;
    int c = idx % DM;
    const float invM = 1.0f / (float)MROWS;
    float mean = stats[c] * invM;
    float var = stats[DM + c] * invM - mean * mean;
    float iv = rsqrtf(var + 1e-5f);
    float val = (u[idx] - mean) * iv * g[c] + be[c];
    u[idx] = val;
    uh[idx] = __float2half(val);
}

// ---------------------------------------------------------------------------
// Misc remap / transposes
// ---------------------------------------------------------------------------
__global__ __launch_bounds__(256) void remap_embed_kernel(
    const float* __restrict__ h, const float* __restrict__ Wpos,
    float* __restrict__ u, __half* __restrict__ uh)
{
    int idx = blockIdx.x * 256 + threadIdx.x;
    int ru = idx / DM, d = idx % DM;
    int bv = ru >> 6, n = ru & 63;
    int b = bv / 7, v = bv % 7;
    int rh = (b * 64 + n) * 7 + v;
    float val = h[(size_t)rh * DM + d] + Wpos[n * DM + d];
    u[idx] = val;
    uh[idx] = __float2half(val);
}

__global__ void transpose_h_kernel(const float* __restrict__ h, float* __restrict__ out)
{
    __shared__ float tile[32][33];
    int bv = blockIdx.z, b = bv / 7, v = bv % 7;
    int d0 = blockIdx.x * 32, n0 = blockIdx.y * 32;
#pragma unroll
    for (int i = 0; i < 32; i += 8) {
        int n = n0 + threadIdx.y + i;
        int d = d0 + threadIdx.x;
        tile[threadIdx.y + i][threadIdx.x] = h[((size_t)(b * 64 + n) * 7 + v) * DM + d];
    }
    __syncthreads();
#pragma unroll
    for (int i = 0; i < 32; i += 8) {
        int d = d0 + threadIdx.y + i;
        int n = n0 + threadIdx.x;
        out[((size_t)bv * DM + d) * LSEQ + n] = tile[threadIdx.x][threadIdx.y + i];
    }
}

__global__ void transpose_z_kernel(const float* __restrict__ u, float* __restrict__ out)
{
    __shared__ float tile[32][33];
    int bv = blockIdx.z;
    int d0 = blockIdx.x * 32, n0 = blockIdx.y * 32;
#pragma unroll
    for (int i = 0; i < 32; i += 8) {
        int n = n0 + threadIdx.y + i;
        int d = d0 + threadIdx.x;
        tile[threadIdx.y + i][threadIdx.x] = u[(size_t)(bv * 64 + n) * DM + d];
    }
    __syncthreads();
#pragma unroll
    for (int i = 0; i < 32; i += 8) {
        int d = d0 + threadIdx.y + i;
        int n = n0 + threadIdx.x;
        out[((size_t)bv * DM + d) * LSEQ + n] = tile[threadIdx.x][threadIdx.y + i];
    }
}

// ---------------------------------------------------------------------------

extern "C" void kernel_launch(void* const* d_in, const int* in_sizes, int n_in,
                              void* d_out, int out_size)
{
    const float* x    = (const float*)d_in[0];
    const float* Wp   = (const float*)d_in[1];
    const float* bp   = (const float*)d_in[2];
    const float* Wpos = (const float*)d_in[3];
    const float* Wq   = (const float*)d_in[4];
    const float* bq   = (const float*)d_in[5];
    const float* Wk   = (const float*)d_in[6];
    const float* bk   = (const float*)d_in[7];
    const float* Wv   = (const float*)d_in[8];
    const float* bv_  = (const float*)d_in[9];
    const float* Wo   = (const float*)d_in[10];
    const float* bo   = (const float*)d_in[11];
    const float* g1   = (const float*)d_in[12];
    const float* be1  = (const float*)d_in[13];
    const float* W1   = (const float*)d_in[14];
    const float* b1   = (const float*)d_in[15];
    const float* W2   = (const float*)d_in[16];
    const float* b2   = (const float*)d_in[17];
    const float* g2   = (const float*)d_in[18];
    const float* be2  = (const float*)d_in[19];

    float* out      = (float*)d_out;
    float* out_z    = out;
    float* out_h    = out + OUTSZ;
    float* out_attn = out + 2 * (size_t)OUTSZ;

    float *u, *q, *k, *v, *t, *sc, *st;
    __half *uh, *oh, *ffh, *wqt, *wkt, *wvt, *wot, *w1t, *w2t;
    cudaGetSymbolAddress((void**)&u,  g_u);
    cudaGetSymbolAddress((void**)&uh, g_uh);
    cudaGetSymbolAddress((void**)&q,  g_q);
    cudaGetSymbolAddress((void**)&k,  g_k);
    cudaGetSymbolAddress((void**)&v,  g_v);
    cudaGetSymbolAddress((void**)&oh, g_oh);
    cudaGetSymbolAddress((void**)&t,  g_t);
    cudaGetSymbolAddress((void**)&ffh, g_ffh);
    cudaGetSymbolAddress((void**)&sc, g_scores);
    cudaGetSymbolAddress((void**)&st, g_stats);
    cudaGetSymbolAddress((void**)&wqt, g_wqt);
    cudaGetSymbolAddress((void**)&wkt, g_wkt);
    cudaGetSymbolAddress((void**)&wvt, g_wvt);
    cudaGetSymbolAddress((void**)&wot, g_wot);
    cudaGetSymbolAddress((void**)&w1t, g_w1t);
    cudaGetSymbolAddress((void**)&w2t, g_w2t);

    cudaFuncSetAttribute(attn_kernel, cudaFuncAttributeMaxDynamicSharedMemorySize, 49920);

    const dim3 blk(256);
    const int elemBlocks = (MROWS * DM) / 256;
    const dim3 tgrid(24, 2, BH);
    const dim3 tblk32(32, 8);
    const dim3 gD(DM / 128, MROWS / 128);   // (6, 224)
    const dim3 gF(DF / 128, MROWS / 128);   // (24, 224)
    const dim3 gdd(DM / 32, DM / 32);
    const dim3 g1d(DF / 32, DM / 32);
    const dim3 g2d(DM / 32, DF / 32);

    // Launch order arranged so launch #5 (ncu -s 5 -c 1) is the first hgemm.
    wtrans_kernel<<<gdd, tblk32>>>(Wq, wqt, DM, DM);                               // 0
    gemm_kernel<<<dim3(DM / 128, MROWS / 128), blk>>>(x, Wp, bp, t, MROWS, DM, 16);// 1
    remap_embed_kernel<<<elemBlocks, blk>>>(t, Wpos, u, uh);                       // 2
    transpose_h_kernel<<<tgrid, tblk32>>>(t, out_h);                               // 3
    wtrans_kernel<<<gdd, tblk32>>>(Wk, wkt, DM, DM);                               // 4
    hgemm<0, 1, 0><<<gD, blk>>>(uh, wqt, bq, q, nullptr, DM, DM);                  // 5 <- profiled

    // remaining weight transposes
    wtrans_kernel<<<gdd, tblk32>>>(Wv, wvt, DM, DM);
    wtrans_kernel<<<gdd, tblk32>>>(Wo, wot, DM, DM);
    wtrans_kernel<<<g1d, tblk32>>>(W1, w1t, DM, DF);
    wtrans_kernel<<<g2d, tblk32>>>(W2, w2t, DF, DM);
    for (int l = 1; l < 3; l++) {
        wtrans_kernel<<<gdd, tblk32>>>(Wq + (size_t)l * DM * DM, wqt + (size_t)l * DM * DM, DM, DM);
        wtrans_kernel<<<gdd, tblk32>>>(Wk + (size_t)l * DM * DM, wkt + (size_t)l * DM * DM, DM, DM);
        wtrans_kernel<<<gdd, tblk32>>>(Wv + (size_t)l * DM * DM, wvt + (size_t)l * DM * DM, DM, DM);
        wtrans_kernel<<<gdd, tblk32>>>(Wo + (size_t)l * DM * DM, wot + (size_t)l * DM * DM, DM, DM);
        wtrans_kernel<<<g1d, tblk32>>>(W1 + (size_t)l * DM * DF, w1t + (size_t)l * DM * DF, DM, DF);
        wtrans_kernel<<<g2d, tblk32>>>(W2 + (size_t)l * DF * DM, w2t + (size_t)l * DF * DM, DF, DM);
    }

    for (int l = 0; l < 3; l++) {
        if (l > 0)
            hgemm<0, 1, 0><<<gD, blk>>>(uh, wqt + (size_t)l * DM * DM, bq + l * DM, q, nullptr, DM, DM);
        hgemm<0, 1, 0><<<gD, blk>>>(uh, wkt + (size_t)l * DM * DM, bk + l * DM, k, nullptr, DM, DM);
        hgemm<0, 1, 0><<<gD, blk>>>(uh, wvt + (size_t)l * DM * DM, bv_ + l * DM, v, nullptr, DM, DM);

        attn_kernel<<<BH * NHEAD, 256, 49920>>>(
            q, k, v, sc, oh, (l == 2) ? out_attn : nullptr, (l > 0) ? 1 : 0);

        hgemm<0, 1, 0><<<gD, blk>>>(oh, wot + (size_t)l * DM * DM, bo + l * DM, t, nullptr, DM, DM);

        zero_stats_kernel<<<6, 256>>>(st);
        bn_add_stats_kernel<<<MROWS / 128, 256>>>(u, t, st);
        bn_norm_kernel<<<elemBlocks, blk>>>(u, uh, st, g1 + l * DM, be1 + l * DM);

        hgemm<1, 0, 1><<<gF, blk>>>(uh, w1t + (size_t)l * DM * DF, b1 + l * DF, nullptr, ffh, DF, DM);
        hgemm<0, 1, 0><<<gD, blk>>>(ffh, w2t + (size_t)l * DF * DM, b2 + l * DM, t, nullptr, DM, DF);

        zero_stats_kernel<<<6, 256>>>(st);
        bn_add_stats_kernel<<<MROWS / 128, 256>>>(u, t, st);
        bn_norm_kernel<<<elemBlocks, blk>>>(u, uh, st, g2 + l * DM, be2 + l * DM);
    }

    transpose_z_kernel<<<tgrid, tblk32>>>(u, out_z);
}